// round 13
// baseline (speedup 1.0000x reference)
#include <cuda_runtime.h>

// 2-layer LSTM (H=30, IN=1) + linear head, B=512, T=2048.
// Skeleton (R12, 815us): block = 1 element, 128 thr = 4 warps, QUAD layout
// (g = tid&3: 0=i,1=f,2=g,3=o; u = tid>>2; units 30,31 pad). Weight rows
// register-resident f32x2, sigmoid lanes pre-scaled by 0.5 (tanh form).
// All activations = hardware tanh.approx.f32. Iter n: L1 step n + L2 step
// n-1 fused, ONE __syncthreads/iter, ping-pong buffers. FC folded into lane
// 127 (w2i=0, w2h=w_fc, b2=bfc -> its pre2 IS out[n-2]).
// This round (slot surgery; loaded SMs are ~92% issue-bound):
//  (a) biases initialize the dot accumulators (a0=(xb,0), e0=(b2,0)) ->
//      post-reduce fadds deleted, reduce chain -4 cyc each.
//  (b) lane 127's b2 = bfc -> emit is a bare predicated store of pre2.
//  (c) x loaded as one LDS.128 per 4 iterations (n=0..3 peeled so the
//      steady window n=4..2047 is float4-aligned).

#define Hs 30
#define Ts 2048
#define Bs 512

typedef unsigned long long ull;

__device__ __forceinline__ ull pk(float lo, float hi) {
    ull r; asm("mov.b64 %0, {%1, %2};" : "=l"(r) : "f"(lo), "f"(hi)); return r;
}
__device__ __forceinline__ void fma2(ull& d, ull a, ull b) {
    asm("fma.rn.f32x2 %0, %1, %2, %3;" : "=l"(d) : "l"(a), "l"(b), "l"(d));
}
__device__ __forceinline__ ull add2(ull a, ull b) {
    ull r; asm("add.rn.f32x2 %0, %1, %2;" : "=l"(r) : "l"(a), "l"(b)); return r;
}
__device__ __forceinline__ float hadd(ull a) {
    float lo, hi; asm("mov.b64 {%0, %1}, %2;" : "=f"(lo), "=f"(hi) : "l"(a)); return lo + hi;
}
__device__ __forceinline__ float tanha(float x) {
    float y; asm("tanh.approx.f32 %0, %1;" : "=f"(y) : "f"(x)); return y;
}
__device__ __forceinline__ float act(float p, float aa, float cc) {
    return fmaf(aa, tanha(p), cc);   // sigmoid lanes: 0.5*t+0.5; g lane: t
}

// One fused iteration. Reads H1R=h1[n-1], H2R=h2[n-2]; writes H1W=h1[n],
// H2W=h2[n-1]. Lane 127 (w2i=0, w2h=w_fc, b2=bfc): pre2 == out[n-2].
#define ITER(H1R, H2R, H1W, H2W, XV, OUTP, DO_EMIT) { \
    const ulonglong2* hp1 = (const ulonglong2*)(H1R); \
    const ulonglong2* hp2 = (const ulonglong2*)(H2R); \
    ull a0 = pk(fmaf((XV), k0, b1), 0.0f); \
    ull e0 = pk(b2e, 0.0f); \
    ull a1 = 0ull, e1 = 0ull, d0 = 0ull, d1 = 0ull; \
    _Pragma("unroll") \
    for (int k = 0; k < 7; k++) { \
        ulonglong2 v1 = hp1[k]; \
        ulonglong2 v2 = hp2[k]; \
        fma2(a0, w1p[2 * k],     v1.x); \
        fma2(a1, w1p[2 * k + 1], v1.y); \
        fma2(e0, w2i[2 * k],     v1.x); \
        fma2(e1, w2i[2 * k + 1], v1.y); \
        fma2(d0, w2h[2 * k],     v2.x); \
        fma2(d1, w2h[2 * k + 1], v2.y); \
    } \
    { ull v1t = ((const ull*)(H1R))[14], v2t = ((const ull*)(H2R))[14]; \
      fma2(a0, w1p[14], v1t); \
      fma2(e0, w2i[14], v1t); \
      fma2(d0, w2h[14], v2t); } \
    float pre1 = hadd(add2(a0, a1)); \
    float pre2 = hadd(add2(add2(e0, e1), add2(d0, d1))); \
    if (DO_EMIT) { if (tid == 127) *(OUTP) = pre2; } \
    float av = act(pre1, aa, cc); \
    float zv = act(pre2, aa, cc); \
    { \
        float gi = __shfl_sync(0xffffffffu, av, base); \
        float gf = __shfl_sync(0xffffffffu, av, base + 1); \
        float gg = __shfl_sync(0xffffffffu, av, base + 2); \
        c1 = fmaf(gf, c1, gi * gg); \
        if (g == 3) (H1W)[u] = av * tanha(c1); \
    } \
    { \
        float qi = __shfl_sync(0xffffffffu, zv, base); \
        float qf = __shfl_sync(0xffffffffu, zv, base + 1); \
        float qg = __shfl_sync(0xffffffffu, zv, base + 2); \
        c2 = fmaf(qf, c2, qi * qg); \
        if (g == 3) (H2W)[u] = zv * tanha(c2); \
    } \
    __syncthreads(); \
}

__global__ void __launch_bounds__(128, 4) lstm_kernel(
    const float* __restrict__ x,
    const float* __restrict__ w_ih1, const float* __restrict__ w_hh1,
    const float* __restrict__ b_ih1, const float* __restrict__ b_hh1,
    const float* __restrict__ w_ih2, const float* __restrict__ w_hh2,
    const float* __restrict__ b_ih2, const float* __restrict__ b_hh2,
    const float* __restrict__ w_fc,  const float* __restrict__ b_fc,
    float* __restrict__ out)
{
    __shared__ __align__(16) float sx[Ts];
    __shared__ __align__(16) float h1A[32], h1B[32];
    __shared__ __align__(16) float h2A[32], h2B[32];

    const int tid  = threadIdx.x;
    const int g    = tid & 3;
    const int u    = tid >> 2;
    const int lane = tid & 31;
    const int base = lane & ~3;
    const int b    = blockIdx.x;

    {   // coalesced x preload
        const float4* xb4 = (const float4*)(x + (size_t)b * Ts);
        float4* sx4 = (float4*)sx;
        #pragma unroll
        for (int i = 0; i < Ts / 4 / 128; i++) sx4[tid + i * 128] = xb4[tid + i * 128];
    }
    if (tid < 32) {
        h1A[tid] = 0.0f; h1B[tid] = 0.0f;
        h2A[tid] = 0.0f; h2B[tid] = 0.0f;
    }

    // Per-lane input scale: sigmoid lanes 0.5 (tanh(x/2) form), g lane 1.0.
    const float s = (g == 2) ? 1.0f : 0.5f;
    const bool  fc_lane = (tid == 127);

    // Register-resident weight rows, PRE-SCALED by s. FC lane (127):
    // w2i = 0, w2h = w_fc (unscaled), b2e = bfc -> its pre2 = out[n-2].
    const int row = g * Hs + ((u < Hs) ? u : Hs - 1);
    ull w1p[15], w2i[15], w2h[15];
    {
        const float* r1  = w_hh1 + row * Hs;
        const float* r2i = w_ih2 + row * Hs;
        const float* r2h = fc_lane ? w_fc : (w_hh2 + row * Hs);
        const float  s2i = fc_lane ? 0.0f : s;
        const float  s2h = fc_lane ? 1.0f : s;
        #pragma unroll
        for (int k = 0; k < 15; k++) {
            w1p[k] = pk(s * r1[2 * k],    s * r1[2 * k + 1]);
            w2i[k] = pk(s2i * r2i[2 * k], s2i * r2i[2 * k + 1]);
            w2h[k] = pk(s2h * r2h[2 * k], s2h * r2h[2 * k + 1]);
        }
    }
    const float k0  = s * w_ih1[row];
    const float b1  = s * (b_ih1[row] + b_hh1[row]);
    const float bfc = b_fc[0];
    const float b2e = fc_lane ? bfc : s * (b_ih2[row] + b_hh2[row]);

    const float aa = (g == 2) ? 1.0f : 0.5f;
    const float cc = (g == 2) ? 0.0f : 0.5f;

    float c1 = 0.0f, c2 = 0.0f;
    float* __restrict__ outb = out + (size_t)b * Ts;

    __syncthreads();

    // ---- Prologue n = 0: L1 step 0 only (h1[-1]=0) -> h1B ----
    {
        float av = act(fmaf(sx[0], k0, b1), aa, cc);
        float gi = __shfl_sync(0xffffffffu, av, base);
        float gg = __shfl_sync(0xffffffffu, av, base + 2);
        c1 = gi * gg;
        if (g == 3) h1B[u] = av * tanha(c1);
        __syncthreads();
    }

    // ---- Peeled n = 1..3 (scalar x loads; aligns steady window to 16B) ----
    ITER(h1B, h2B, h1A, h2A, sx[1], outb,     false);   // n=1 (h2[-1]=0)
    ITER(h1A, h2A, h1B, h2B, sx[2], outb,     true);    // n=2 -> out[0]
    ITER(h1B, h2B, h1A, h2A, sx[3], outb + 1, true);    // n=3 -> out[1]

    // ---- Steady: n = 4..2047 in aligned float4 groups ----
    const float4* xq4 = (const float4*)sx;
    float* op = outb + 2;      // out[n-2] at group head
    #pragma unroll 1
    for (int k4 = 1; k4 <= 511; k4++) {
        float4 xq = xq4[k4];
        ITER(h1A, h2A, h1B, h2B, xq.x, op,     true);
        ITER(h1B, h2B, h1A, h2A, xq.y, op + 1, true);
        ITER(h1A, h2A, h1B, h2B, xq.z, op + 2, true);
        ITER(h1B, h2B, h1A, h2A, xq.w, op + 3, true);
        op += 4;
    }
    // After steady: h1A = h1[2047], h2A = h2[2046]; emitted out[0..2045].

    // ---- Epilogue: L2-only step 2047; lane 127 emits out[2046] ----
    {
        const ulonglong2* hp1 = (const ulonglong2*)h1A;
        const ulonglong2* hp2 = (const ulonglong2*)h2A;
        ull e0 = pk(b2e, 0.0f);
        ull e1 = 0ull, d0 = 0ull, d1 = 0ull;
        #pragma unroll
        for (int k = 0; k < 7; k++) {
            ulonglong2 v1 = hp1[k];
            ulonglong2 v2 = hp2[k];
            fma2(e0, w2i[2 * k],     v1.x);
            fma2(e1, w2i[2 * k + 1], v1.y);
            fma2(d0, w2h[2 * k],     v2.x);
            fma2(d1, w2h[2 * k + 1], v2.y);
        }
        fma2(e0, w2i[14], ((const ull*)h1A)[14]);
        fma2(d0, w2h[14], ((const ull*)h2A)[14]);
        float pre2 = hadd(add2(add2(e0, e1), add2(d0, d1)));
        if (tid == 127) outb[Ts - 2] = pre2;
        float zv = act(pre2, aa, cc);
        float qi = __shfl_sync(0xffffffffu, zv, base);
        float qf = __shfl_sync(0xffffffffu, zv, base + 1);
        float qg = __shfl_sync(0xffffffffu, zv, base + 2);
        c2 = fmaf(qf, c2, qi * qg);
        if (g == 3) h2B[u] = zv * tanha(c2);
        __syncthreads();
    }
    // ---- Final: out[2047] = w_fc . h2[2047] + bfc (lane 127 mini-dot) ----
    if (tid == 127) {
        const ulonglong2* hp2 = (const ulonglong2*)h2B;
        ull d0 = 0ull, d1 = 0ull;
        #pragma unroll
        for (int k = 0; k < 7; k++) {
            ulonglong2 v2 = hp2[k];
            fma2(d0, w2h[2 * k],     v2.x);
            fma2(d1, w2h[2 * k + 1], v2.y);
        }
        fma2(d0, w2h[14], ((const ull*)h2B)[14]);
        outb[Ts - 1] = hadd(add2(d0, d1)) + bfc;
    }
}

extern "C" void kernel_launch(void* const* d_in, const int* in_sizes, int n_in,
                              void* d_out, int out_size) {
    (void)in_sizes; (void)n_in; (void)out_size;
    lstm_kernel<<<Bs, 128>>>(
        (const float*)d_in[0],
        (const float*)d_in[1], (const float*)d_in[2],
        (const float*)d_in[3], (const float*)d_in[4],
        (const float*)d_in[5], (const float*)d_in[6],
        (const float*)d_in[7], (const float*)d_in[8],
        (const float*)d_in[9], (const float*)d_in[10],
        (float*)d_out);
}